// round 16
// baseline (speedup 1.0000x reference)
#include <cuda_runtime.h>
#include <cuda_fp16.h>
#include <math.h>

#define N_NODES 2048
#define DMODEL  256
#define NHEAD   8
#define DK      32
#define NEDGE   65536
#define HID     512
#define KSPLIT  8
#define CAPL    256
#define ATILES  ((N_NODES / KSPLIT) / 64)

typedef unsigned long long ull;
typedef unsigned int u32;

// ---- mma / ldmatrix / cp.async helpers ----
__device__ __forceinline__ u32 su32(const void* p) {
    return (u32)__cvta_generic_to_shared(p);
}
__device__ __forceinline__ void ldsm_x4(u32& r0, u32& r1, u32& r2, u32& r3, u32 a) {
    asm volatile("ldmatrix.sync.aligned.m8n8.x4.shared.b16 {%0,%1,%2,%3},[%4];"
                 : "=r"(r0), "=r"(r1), "=r"(r2), "=r"(r3) : "r"(a));
}
__device__ __forceinline__ void ldsm_x4t(u32& r0, u32& r1, u32& r2, u32& r3, u32 a) {
    asm volatile("ldmatrix.sync.aligned.m8n8.x4.trans.shared.b16 {%0,%1,%2,%3},[%4];"
                 : "=r"(r0), "=r"(r1), "=r"(r2), "=r"(r3) : "r"(a));
}
__device__ __forceinline__ void mma16816h(float& c0, float& c1, float& c2, float& c3,
                                          u32 a0, u32 a1, u32 a2, u32 a3, u32 b0, u32 b1) {
    asm volatile("mma.sync.aligned.m16n8k16.row.col.f32.f16.f16.f32 "
                 "{%0,%1,%2,%3},{%4,%5,%6,%7},{%8,%9},{%0,%1,%2,%3};"
                 : "+f"(c0), "+f"(c1), "+f"(c2), "+f"(c3)
                 : "r"(a0), "r"(a1), "r"(a2), "r"(a3), "r"(b0), "r"(b1));
}
__device__ __forceinline__ float ex2f(float x) {
    float r; asm("ex2.approx.f32 %0,%1;" : "=f"(r) : "f"(x)); return r;
}
__device__ __forceinline__ u32 ex2h2(u32 a) {
    u32 r; asm("ex2.approx.f16x2 %0,%1;" : "=r"(r) : "r"(a)); return r;
}
__device__ __forceinline__ u32 f2h2(float lo, float hi) {
    __half2 h = __floats2half2_rn(lo, hi);
    return *(u32*)&h;
}
__device__ __forceinline__ float hlo(u32 w) { __half2 h = *(__half2*)&w; return __low2float(h); }
__device__ __forceinline__ float hhi(u32 w) { __half2 h = *(__half2*)&w; return __high2float(h); }
__device__ __forceinline__ __half2 ash2(u32 w) { return *(__half2*)&w; }
__device__ __forceinline__ void cp16(u32 dst, const void* src) {
    asm volatile("cp.async.ca.shared.global [%0],[%1],16;" :: "r"(dst), "l"(src));
}

// ---------------- scratch ----------------
__device__ __half g_hb[N_NODES * DMODEL];
__device__ __half g_Wqb[DMODEL * DMODEL];
__device__ __half g_Wkb[DMODEL * DMODEL];
__device__ __half g_Wvb[DMODEL * DMODEL];
__device__ __half g_Wob[DMODEL * DMODEL];
__device__ __half g_W1b[DMODEL * HID];
__device__ __half g_W2b[HID * DMODEL];
__device__ __half g_Qb[N_NODES * DMODEL];     // pre-scaled by log2e/sqrt(dk)
__device__ __half g_Kb[N_NODES * DMODEL];
__device__ __half g_Vb[N_NODES * DMODEL];
__device__ __half g_attnb[N_NODES * DMODEL];
__device__ __half g_x2b[N_NODES * DMODEL];
__device__ __half g_Gb[N_NODES * HID];
__device__ float g_eb[NEDGE * NHEAD];         // stores 2^(eb*log2e) - 1
__device__ int   g_cnt[N_NODES];              // self-resetting (corr zeroes it)
__device__ u32   g_list[N_NODES * CAPL];
__device__ __half g_parth[KSPLIT * N_NODES * DMODEL];   // f16 O partials
__device__ float g_lp[KSPLIT * N_NODES * NHEAD];
__device__ float g_Y[N_NODES * DMODEL];
__device__ float g_h1[N_NODES * DMODEL];

// ---------------- conv + edge prep ----------------
__global__ __launch_bounds__(256) void prep_kernel(const float* __restrict__ h,
                                                   const float* __restrict__ Wq,
                                                   const float* __restrict__ Wk,
                                                   const float* __restrict__ Wv,
                                                   const float* __restrict__ Wo,
                                                   const float* __restrict__ W1,
                                                   const float* __restrict__ W2,
                                                   const float* __restrict__ ea,
                                                   const float* __restrict__ We,
                                                   const float* __restrict__ be,
                                                   const int*   __restrict__ eidx) {
    int gid = blockIdx.x * 256 + threadIdx.x;
    if (gid < 262144) {
        const float* src; __half* dst; int off;
        if (gid < 131072)      { src = h;  dst = g_hb;  off = gid; }
        else if (gid < 147456) { src = Wq; dst = g_Wqb; off = gid - 131072; }
        else if (gid < 163840) { src = Wk; dst = g_Wkb; off = gid - 147456; }
        else if (gid < 180224) { src = Wv; dst = g_Wvb; off = gid - 163840; }
        else if (gid < 196608) { src = Wo; dst = g_Wob; off = gid - 180224; }
        else if (gid < 229376) { src = W1; dst = g_W1b; off = gid - 196608; }
        else                   { src = W2; dst = g_W2b; off = gid - 229376; }
        float4 v = ((const float4*)src)[off];
        uint2 p;
        p.x = f2h2(v.x, v.y);
        p.y = f2h2(v.z, v.w);
        ((uint2*)dst)[off] = p;
    } else {
        const float L2E = 1.4426950408889634f;
        int e = gid - 262144;
        float a[7];
#pragma unroll
        for (int j = 0; j < 7; j++) a[j] = ea[e * 7 + j];
#pragma unroll
        for (int hh = 0; hh < 8; hh++) {
            float v = be[hh];
#pragma unroll
            for (int j = 0; j < 7; j++) v += a[j] * We[j * 8 + hh];
            g_eb[e * 8 + hh] = ex2f(v * L2E) - 1.f;   // 2^eb' - 1
        }
        int src = eidx[e];
        int dst = eidx[NEDGE + e];
        int pos = atomicAdd(&g_cnt[src], 1);
        if (pos < CAPL) g_list[(size_t)src * CAPL + pos] = ((u32)dst << 16) | (u32)e;
    }
}

// ---------------- fp16 tensor-core GEMM: 32x64 tile, BK=32, cp.async 4-stage ------
__device__ __forceinline__ void gemm_f16_body(const __half* __restrict__ A,
                                              const __half* __restrict__ B,
                                              const float* __restrict__ bias,
                                              const float* __restrict__ R,
                                              float* __restrict__ Cf,
                                              __half* __restrict__ Cb,
                                              int N, int K, int gelu, float oscale,
                                              int bm, int bn) {
    __shared__ __align__(16) __half As[4][32][40];
    __shared__ __align__(16) __half Bs[4][32][72];
    const int tid = threadIdx.x, warp = tid >> 5, lane = tid & 31;
    const int wm = warp & 1, wn = warp >> 1;
    const int lr = lane & 7, lm = lane >> 3;

    const int ar = tid >> 2, ac = tid & 3;
    const int br0 = tid >> 3, bc = tid & 7;
    const int br1 = br0 + 16;

    const u32 sA = su32(&As[0][0][0]);
    const u32 sB = su32(&Bs[0][0][0]);
    const u32 dstA  = sA + ar * 80 + ac * 16;
    const u32 dstB0 = sB + br0 * 144 + bc * 16;
    const u32 dstB1 = sB + br1 * 144 + bc * 16;
    const __half* srcA = A + (size_t)(bm + ar) * K + ac * 8;

    const int Kk = K >> 5;
    float acc[4][4] = {};

    auto issue = [&](int kb, int st) {
        if (kb < Kk) {
            cp16(dstA + st * 2560, srcA + kb * 32);
            cp16(dstB0 + st * 4608, B + (size_t)(kb * 32 + br0) * N + bn + bc * 8);
            cp16(dstB1 + st * 4608, B + (size_t)(kb * 32 + br1) * N + bn + bc * 8);
        }
        asm volatile("cp.async.commit_group;");
    };
    issue(0, 0);
    issue(1, 1);
    issue(2, 2);

    const u32 aBase = sA + (wm * 16 + lr + (lm & 1) * 8) * 80 + (lm >> 1) * 16;
    const u32 bBase = sB + (lr + (lm & 1) * 8) * 144 + (wn * 32 + (lm >> 1) * 8) * 2;

    for (int kb = 0; kb < Kk; kb++) {
        asm volatile("cp.async.wait_group 2;");
        __syncthreads();
        issue(kb + 3, (kb + 3) & 3);
        const u32 aS = aBase + (kb & 3) * 2560;
        const u32 bS = bBase + (kb & 3) * 4608;
#pragma unroll
        for (int ks = 0; ks < 2; ks++) {
            u32 a0, a1, a2, a3;
            ldsm_x4(a0, a1, a2, a3, aS + ks * 32);
#pragma unroll
            for (int ng2 = 0; ng2 < 2; ng2++) {
                u32 b0, b1, b2, b3;
                ldsm_x4t(b0, b1, b2, b3, bS + ks * 16 * 144 + ng2 * 32);
                mma16816h(acc[ng2 * 2][0], acc[ng2 * 2][1], acc[ng2 * 2][2], acc[ng2 * 2][3],
                          a0, a1, a2, a3, b0, b1);
                mma16816h(acc[ng2 * 2 + 1][0], acc[ng2 * 2 + 1][1],
                          acc[ng2 * 2 + 1][2], acc[ng2 * 2 + 1][3],
                          a0, a1, a2, a3, b2, b3);
            }
        }
    }

    const int rr = lane >> 2, cql = 2 * (lane & 3);
    const int r0 = bm + wm * 16 + rr, r1 = r0 + 8;
#pragma unroll
    for (int idx = 0; idx < 4; idx++) {
        const int col = bn + wn * 32 + idx * 8 + cql;
        float b0 = bias[col], b1 = bias[col + 1];
        float o0 = (acc[idx][0] + b0) * oscale, o1 = (acc[idx][1] + b1) * oscale;
        float o2 = (acc[idx][2] + b0) * oscale, o3 = (acc[idx][3] + b1) * oscale;
        if (gelu) {
            o0 *= normcdff(o0); o1 *= normcdff(o1);
            o2 *= normcdff(o2); o3 *= normcdff(o3);
        }
        if (R) {
            o0 += R[(size_t)r0 * N + col]; o1 += R[(size_t)r0 * N + col + 1];
            o2 += R[(size_t)r1 * N + col]; o3 += R[(size_t)r1 * N + col + 1];
        }
        if (Cb) {
            *(u32*)&Cb[(size_t)r0 * N + col] = f2h2(o0, o1);
            *(u32*)&Cb[(size_t)r1 * N + col] = f2h2(o2, o3);
        } else {
            *(float2*)&Cf[(size_t)r0 * N + col] = make_float2(o0, o1);
            *(float2*)&Cf[(size_t)r1 * N + col] = make_float2(o2, o3);
        }
    }
}

__global__ __launch_bounds__(128) void gemm_f16(const __half* __restrict__ A,
                                                const __half* __restrict__ B,
                                                const float* __restrict__ bias,
                                                const float* __restrict__ R,
                                                float* __restrict__ Cf,
                                                __half* __restrict__ Cb,
                                                int N, int K, int gelu) {
    gemm_f16_body(A, B, bias, R, Cf, Cb, N, K, gelu, 1.0f, blockIdx.y * 32, blockIdx.x * 64);
}

__global__ __launch_bounds__(128) void gemm_qkv_f16(const float* __restrict__ bq,
                                                    const float* __restrict__ bk,
                                                    const float* __restrict__ bv) {
    const float SCALE2 = 1.4426950408889634f * 0.17677669529663688f;
    int sel = blockIdx.x >> 2;
    int bn  = (blockIdx.x & 3) * 64;
    const __half* B   = (sel == 0) ? g_Wqb : (sel == 1) ? g_Wkb : g_Wvb;
    const float* bias = (sel == 0) ? bq : (sel == 1) ? bk : bv;
    __half* Cb        = (sel == 0) ? g_Qb : (sel == 1) ? g_Kb : g_Vb;
    float oscale      = (sel == 0) ? SCALE2 : 1.0f;
    gemm_f16_body(g_hb, B, bias, nullptr, nullptr, Cb, DMODEL, DMODEL, 0, oscale,
                  blockIdx.y * 32, bn);
}

// ---------------- dense flash attention: 128 q/block, split-K=8, f16x2 exp ----
__global__ __launch_bounds__(128, 3) void attn_mma(const __half* __restrict__ Qb,
                                                   const __half* __restrict__ Kb,
                                                   const __half* __restrict__ Vb) {
    __shared__ __align__(16) __half Qs[128][40];
    __shared__ __align__(16) __half Ks[3][64][40];
    __shared__ __align__(16) __half Vs[3][64][40];

    const int h     = blockIdx.y;
    const int qb    = blockIdx.x * 128;
    const int chunk = blockIdx.z;
    const int kb0   = chunk * (N_NODES / KSPLIT);
    const int tid = threadIdx.x;
    const int warp = tid >> 5, lane = tid & 31;

#pragma unroll
    for (int i = 0; i < 4; i++) {
        int task = tid + 128 * i;
        int row = task >> 2, ch = task & 3;
        *(uint4*)((char*)&Qs[row][0] + ch * 16) =
            *(const uint4*)((const char*)(Qb + (size_t)(qb + row) * DMODEL + h * DK) + ch * 16);
    }
    __syncthreads();
    const int lr = lane & 7, lm = lane >> 3;
    u32 qa[2][2][4];
#pragma unroll
    for (int s = 0; s < 2; s++) {
        int row = warp * 32 + s * 16 + lr + (lm & 1) * 8;
#pragma unroll
        for (int c = 0; c < 2; c++) {
            u32 a = su32(&Qs[row][c * 16 + (lm >> 1) * 8]);
            ldsm_x4(qa[s][c][0], qa[s][c][1], qa[s][c][2], qa[s][c][3], a);
        }
    }

    const int row0 = tid >> 2, ch0 = tid & 3;
    const int row1 = (tid + 128) >> 2, ch1 = (tid + 128) & 3;
    const u32 kd0 = su32(&Ks[0][row0][0]) + ch0 * 16;
    const u32 kd1 = su32(&Ks[0][row1][0]) + ch1 * 16;
    const u32 vd0 = su32(&Vs[0][row0][0]) + ch0 * 16;
    const u32 vd1 = su32(&Vs[0][row1][0]) + ch1 * 16;

    auto issueT = [&](int kt, int st) {
        if (kt < ATILES) {
            int kb = kb0 + kt * 64;
            cp16(kd0 + st * 5120, (const char*)(Kb + (size_t)(kb + row0) * DMODEL + h * DK) + ch0 * 16);
            cp16(kd1 + st * 5120, (const char*)(Kb + (size_t)(kb + row1) * DMODEL + h * DK) + ch1 * 16);
            cp16(vd0 + st * 5120, (const char*)(Vb + (size_t)(kb + row0) * DMODEL + h * DK) + ch0 * 16);
            cp16(vd1 + st * 5120, (const char*)(Vb + (size_t)(kb + row1) * DMODEL + h * DK) + ch1 * 16);
        }
        asm volatile("cp.async.commit_group;");
    };
    issueT(0, 0);
    issueT(1, 1);

    const u32 kaddr = su32(&Ks[0][lr][lm * 8]);
    const u32 vaddr = su32(&Vs[0][lr + (lm & 1) * 8][(lm >> 1) * 8]);

    float O[2][4][4];
#pragma unroll
    for (int s = 0; s < 2; s++)
#pragma unroll
        for (int t = 0; t < 4; t++)
#pragma unroll
            for (int j = 0; j < 4; j++) O[s][t][j] = 0.f;
    float l[2][2] = {};

    for (int kt = 0; kt < ATILES; kt++) {
        asm volatile("cp.async.wait_group 1;");
        __syncthreads();
        issueT(kt + 2, (kt + 2) % 3);
        const u32 kS = kaddr + (kt % 3) * 5120;
        const u32 vS = vaddr + (kt % 3) * 5120;

        u32 P[2][8][2];
#pragma unroll
        for (int kg = 0; kg < 8; kg++) {
            u32 b0, b1, b2, b3;
            ldsm_x4(b0, b1, b2, b3, kS + kg * 640);
#pragma unroll
            for (int s = 0; s < 2; s++) {
                float c0 = 0.f, c1 = 0.f, c2 = 0.f, c3 = 0.f;
                mma16816h(c0, c1, c2, c3, qa[s][0][0], qa[s][0][1], qa[s][0][2], qa[s][0][3], b0, b1);
                mma16816h(c0, c1, c2, c3, qa[s][1][0], qa[s][1][1], qa[s][1][2], qa[s][1][3], b2, b3);
                u32 p01 = ex2h2(f2h2(c0, c1));
                u32 p23 = ex2h2(f2h2(c2, c3));
                l[s][0] += hlo(p01) + hhi(p01);
                l[s][1] += hlo(p23) + hhi(p23);
                P[s][kg][0] = p01;
                P[s][kg][1] = p23;
            }
        }

#pragma unroll
        for (int ck = 0; ck < 4; ck++) {
#pragma unroll
            for (int tp = 0; tp < 2; tp++) {
                u32 v0, v1, v2, v3;
                ldsm_x4t(v0, v1, v2, v3, vS + ck * 1280 + tp * 32);
#pragma unroll
                for (int s = 0; s < 2; s++) {
                    u32 a0 = P[s][2 * ck][0], a1 = P[s][2 * ck][1];
                    u32 a2 = P[s][2 * ck + 1][0], a3 = P[s][2 * ck + 1][1];
                    mma16816h(O[s][2 * tp][0], O[s][2 * tp][1], O[s][2 * tp][2], O[s][2 * tp][3],
                              a0, a1, a2, a3, v0, v1);
                    mma16816h(O[s][2 * tp + 1][0], O[s][2 * tp + 1][1],
                              O[s][2 * tp + 1][2], O[s][2 * tp + 1][3],
                              a0, a1, a2, a3, v2, v3);
                }
            }
        }
    }

    const int cql = 2 * (lane & 3);
    __half* part = g_parth + (size_t)chunk * N_NODES * DMODEL;
#pragma unroll
    for (int s = 0; s < 2; s++) {
        float l0 = l[s][0], l1 = l[s][1];
        l0 += __shfl_xor_sync(0xffffffffu, l0, 1);
        l0 += __shfl_xor_sync(0xffffffffu, l0, 2);
        l1 += __shfl_xor_sync(0xffffffffu, l1, 1);
        l1 += __shfl_xor_sync(0xffffffffu, l1, 2);
        const int r0 = qb + warp * 32 + s * 16 + (lane >> 2);
        const int r1 = r0 + 8;
#pragma unroll
        for (int t = 0; t < 4; t++) {
            int col = h * DK + t * 8 + cql;
            *(u32*)&part[(size_t)r0 * DMODEL + col] = f2h2(O[s][t][0], O[s][t][1]);
            *(u32*)&part[(size_t)r1 * DMODEL + col] = f2h2(O[s][t][2], O[s][t][3]);
        }
        if ((lane & 3) == 0) {
            g_lp[((size_t)chunk * N_NODES + r0) * NHEAD + h] = l0;
            g_lp[((size_t)chunk * N_NODES + r1) * NHEAD + h] = l1;
        }
    }
}

// ---------------- sparse bias correction + combine -> f16 attn ----------------
// block 64 = 2 warps = 1 query x 2 head-halves. lane = h_local*8 + g,
// h = warp*4 + h_local, lane owns dims [g*4, g*4+4). half2 math throughout.
__global__ __launch_bounds__(64) void corr_kernel(const __half* __restrict__ Qb,
                                                  const __half* __restrict__ Kb,
                                                  const __half* __restrict__ Vb) {
    __shared__ u32 slist[CAPL];
    __shared__ u32 wlist[CAPL];
    __shared__ int scnt;
    const int warp = threadIdx.x >> 5;   // head half
    const int q    = blockIdx.x;
    const int lane = threadIdx.x & 31;
    const int hl = lane >> 3, g = lane & 7;
    const int h = warp * 4 + hl;
    const u32 lmask_lt = (1u << lane) - 1u;

    if (threadIdx.x == 0) { scnt = g_cnt[q]; g_cnt[q] = 0; }   // self-reset
    __syncthreads();
    int cnt = scnt;
    if (cnt > CAPL) cnt = CAPL;

    // Q slice (pre-scaled) as half2
    __half2 qh0, qh1;
    {
        uint2 wq = *(const uint2*)(Qb + (size_t)q * DMODEL + h * DK + g * 4);
        qh0 = ash2(wq.x);
        qh1 = ash2(wq.y);
    }

    // both warps load the full list (identical values - benign)
    for (int i = lane; i < cnt; i += 32)
        slist[i] = g_list[(size_t)q * CAPL + i];
    __syncwarp();

    // dedup (winner = max (dst<<16)|e per dst) + compact; duplicated per warp
    int ncnt = 0;
    for (int base = 0; base < cnt; base += 32) {
        int i = base + lane;
        u32 v = 0;
        bool win = false;
        if (i < cnt) {
            v = slist[i];
            win = true;
            for (int j = 0; j < cnt; j++) {
                u32 u = slist[j];
                if (((u ^ v) & 0xFFFF0000u) == 0 && u > v) win = false;
            }
        }
        u32 m = __ballot_sync(0xffffffffu, win);
        if (win) wlist[ncnt + __popc(m & lmask_lt)] = v;
        ncnt += __popc(m);
    }
    __syncwarp();

    __half2 Oa = __float2half2_rn(0.f), Ob = __float2half2_rn(0.f);
    float lacc = 0.f;

    uint2 kA[4], vA[4];
    float eA[4];
    auto loadb = [&](int base, uint2* kk, uint2* vv, float* ee) {
#pragma unroll
        for (int j = 0; j < 4; j++) {
            int idx = base + j;
            if (idx < ncnt) {                        // warp-uniform
                u32 v = wlist[idx];
                int k    = (int)(v >> 16);
                int widx = (int)(v & 0xFFFFu);
                kk[j] = *(const uint2*)(Kb + (size_t)k * DMODEL + h * DK + g * 4);
                vv[j] = *(const uint2*)(Vb + (size_t)k * DMODEL + h * DK + g * 4);
                ee[j] = g_eb[(size_t)widx * 8 + h];  // 2^eb - 1
            }
        }
    };
    loadb(0, kA, vA, eA);

    for (int i = 0; i < ncnt; i += 4) {
        uint2 kB[4], vB[4];
        float eB[4];
        loadb(i + 4, kB, vB, eB);                    // prefetch next batch
#pragma unroll
        for (int j = 0; j < 4; j++) {
            if (i + j >= ncnt) break;                // warp-uniform
            __half2 d = __hmul2(qh0, ash2(kA[j].x));
            d = __hfma2(qh1, ash2(kA[j].y), d);
            float s = __low2float(d) + __high2float(d);
            s += __shfl_xor_sync(0xffffffffu, s, 1);
            s += __shfl_xor_sync(0xffffffffu, s, 2);
            s += __shfl_xor_sync(0xffffffffu, s, 4);
            float pd = ex2f(s) * eA[j];              // 2^s * (2^eb - 1)
            lacc += pd;
            __half2 pdh = __float2half2_rn(pd);
            Oa = __hfma2(pdh, ash2(vA[j].x), Oa);
            Ob = __hfma2(pdh, ash2(vA[j].y), Ob);
        }
#pragma unroll
        for (int j = 0; j < 4; j++) { kA[j] = kB[j]; vA[j] = vB[j]; eA[j] = eB[j]; }
    }

    // reduce lacc across the 8-lane head group (all lanes get it)
    lacc += __shfl_xor_sync(0xffffffffu, lacc, 1);
    lacc += __shfl_xor_sync(0xffffffffu, lacc, 2);
    lacc += __shfl_xor_sync(0xffffffffu, lacc, 4);

    float O4[4] = {__low2float(Oa), __high2float(Oa), __low2float(Ob), __high2float(Ob)};

    float ltot = lacc;
#pragma unroll
    for (int c = 0; c < KSPLIT; c++)
        ltot += g_lp[((size_t)c * N_NODES + q) * NHEAD + h];
    const int col = h * DK + g * 4;
#pragma unroll
    for (int c = 0; c < KSPLIT; c++) {
        uint2 p = *(const uint2*)(g_parth + ((size_t)c * N_NODES + q) * DMODEL + col);
        O4[0] += hlo(p.x); O4[1] += hhi(p.x);
        O4[2] += hlo(p.y); O4[3] += hhi(p.y);
    }
    float inv = 1.f / ltot;
    uint2 px;
    px.x = f2h2(O4[0] * inv, O4[1] * inv);
    px.y = f2h2(O4[2] * inv, O4[3] * inv);
    *(uint2*)&g_attnb[(size_t)q * DMODEL + col] = px;
}

// ---------------- fused double LayerNorm ----------------
__global__ __launch_bounds__(256) void ln_kernel(const float* __restrict__ Y,
                                                 const float* __restrict__ g1,
                                                 const float* __restrict__ b1,
                                                 const float* __restrict__ g2,
                                                 const float* __restrict__ b2,
                                                 float* __restrict__ H1,
                                                 __half* __restrict__ X2h) {
    const int lane = threadIdx.x & 31;
    const int row  = blockIdx.x * 8 + (threadIdx.x >> 5);
    const float4* y4 = (const float4*)(Y + (size_t)row * DMODEL);
    float v[8];
    {
        float4 a = y4[lane * 2], b = y4[lane * 2 + 1];
        v[0] = a.x; v[1] = a.y; v[2] = a.z; v[3] = a.w;
        v[4] = b.x; v[5] = b.y; v[6] = b.z; v[7] = b.w;
    }

    float s = 0.f;
#pragma unroll
    for (int j = 0; j < 8; j++) s += v[j];
#pragma unroll
    for (int o = 16; o; o >>= 1) s += __shfl_xor_sync(0xffffffffu, s, o);
    float mu = s * (1.f / 256.f);
    float q = 0.f;
#pragma unroll
    for (int j = 0; j < 8; j++) { float d = v[j] - mu; q += d * d; }
#pragma unroll
    for (int o = 16; o; o >>= 1) q += __shfl_xor_sync(0xffffffffu, q, o);
    float rs = rsqrtf(q * (1.f / 256.f) + 1e-5f);

    const int c0 = lane * 8;
    float hv[8];
#pragma unroll
    for (int j = 0; j < 8; j++)
        hv[j] = (v[j] - mu) * rs * g1[c0 + j] + b1[c0 + j];
    {
        float4* h4 = (float4*)(H1 + (size_t)row * DMODEL + c0);
        h4[0] = make_float4(hv[0], hv[1], hv[2], hv[3]);
        h4[1] = make_float4(hv[4], hv[5], hv[6], hv[7]);
    }

    s = 0.f;
#pragma unroll
    for (int j = 0; j < 8; j++) s += hv[j];
#pragma unroll
    for (int o = 16; o; o >>= 1) s += __shfl_xor_sync(0xffffffffu, s, o);
    mu = s * (1.f / 256.f);
    q = 0.f;
#pragma unroll
    for (int j = 0; j < 8; j++) { float d = hv[j] - mu; q += d * d; }
#pragma unroll
    for (int o = 16; o; o >>= 1) q += __shfl_xor_sync(0xffffffffu, q, o);
    rs = rsqrtf(q * (1.f / 256.f) + 1e-5f);

    float x[8];
#pragma unroll
    for (int j = 0; j < 8; j++)
        x[j] = (hv[j] - mu) * rs * g2[c0 + j] + b2[c0 + j];
    uint4 px;
    px.x = f2h2(x[0], x[1]);
    px.y = f2h2(x[2], x[3]);
    px.z = f2h2(x[4], x[5]);
    px.w = f2h2(x[6], x[7]);
    *(uint4*)&X2h[(size_t)row * DMODEL + c0] = px;
}

// ---------------- launch ----------------
extern "C" void kernel_launch(void* const* d_in, const int* in_sizes, int n_in,
                              void* d_out, int out_size) {
    const float* h    = (const float*)d_in[0];
    const float* ea   = (const float*)d_in[1];
    const float* Wq   = (const float*)d_in[2];
    const float* bq   = (const float*)d_in[3];
    const float* Wk   = (const float*)d_in[4];
    const float* bk   = (const float*)d_in[5];
    const float* Wv   = (const float*)d_in[6];
    const float* bv   = (const float*)d_in[7];
    const float* Wo   = (const float*)d_in[8];
    const float* bo   = (const float*)d_in[9];
    const float* We   = (const float*)d_in[10];
    const float* be   = (const float*)d_in[11];
    const float* ln1g = (const float*)d_in[12];
    const float* ln1b = (const float*)d_in[13];
    const float* flng = (const float*)d_in[14];
    const float* flnb = (const float*)d_in[15];
    const float* W1   = (const float*)d_in[16];
    const float* b1   = (const float*)d_in[17];
    const float* W2   = (const float*)d_in[18];
    const float* b2   = (const float*)d_in[19];
    const int*   eidx = (const int*)d_in[20];
    float* out = (float*)d_out;

    __half *pQb, *pKb, *pVb, *pAttnb, *pX2b, *pGb, *pWob, *pW1b, *pW2b;
    float *pY, *pH1;
    cudaGetSymbolAddress((void**)&pQb,    g_Qb);
    cudaGetSymbolAddress((void**)&pKb,    g_Kb);
    cudaGetSymbolAddress((void**)&pVb,    g_Vb);
    cudaGetSymbolAddress((void**)&pAttnb, g_attnb);
    cudaGetSymbolAddress((void**)&pX2b,   g_x2b);
    cudaGetSymbolAddress((void**)&pGb,    g_Gb);
    cudaGetSymbolAddress((void**)&pWob,   g_Wob);
    cudaGetSymbolAddress((void**)&pW1b,   g_W1b);
    cudaGetSymbolAddress((void**)&pW2b,   g_W2b);
    cudaGetSymbolAddress((void**)&pY,     g_Y);
    cudaGetSymbolAddress((void**)&pH1,    g_h1);

    prep_kernel<<<1280, 256>>>(h, Wq, Wk, Wv, Wo, W1, W2, ea, We, be, eidx);

    gemm_qkv_f16<<<dim3(12, 64), 128>>>(bq, bk, bv);

    attn_mma<<<dim3(N_NODES / 128, NHEAD, KSPLIT), 128>>>(pQb, pKb, pVb);
    corr_kernel<<<N_NODES, 64>>>(pQb, pKb, pVb);

    gemm_f16<<<dim3(4, 64), 128>>>(pAttnb, pWob, bo, h, pY, nullptr,
                                   DMODEL, DMODEL, 0);

    ln_kernel<<<N_NODES / 8, 256>>>(pY, ln1g, ln1b, flng, flnb, pH1, pX2b);

    gemm_f16<<<dim3(8, 64), 128>>>(pX2b, pW1b, b1, nullptr, nullptr, pGb,
                                   HID, DMODEL, 1);
    gemm_f16<<<dim3(4, 64), 128>>>(pGb, pW2b, b2, pH1, out, nullptr,
                                   DMODEL, HID, 0);
}

// round 17
// speedup vs baseline: 1.0662x; 1.0662x over previous
#include <cuda_runtime.h>
#include <cuda_fp16.h>
#include <math.h>

#define N_NODES 2048
#define DMODEL  256
#define NHEAD   8
#define DK      32
#define NEDGE   65536
#define HID     512
#define KSPLIT  8
#define CAPL    256
#define ATILES  ((N_NODES / KSPLIT) / 64)

typedef unsigned long long ull;
typedef unsigned int u32;

// ---- mma / ldmatrix / cp.async helpers ----
__device__ __forceinline__ u32 su32(const void* p) {
    return (u32)__cvta_generic_to_shared(p);
}
__device__ __forceinline__ void ldsm_x4(u32& r0, u32& r1, u32& r2, u32& r3, u32 a) {
    asm volatile("ldmatrix.sync.aligned.m8n8.x4.shared.b16 {%0,%1,%2,%3},[%4];"
                 : "=r"(r0), "=r"(r1), "=r"(r2), "=r"(r3) : "r"(a));
}
__device__ __forceinline__ void ldsm_x4t(u32& r0, u32& r1, u32& r2, u32& r3, u32 a) {
    asm volatile("ldmatrix.sync.aligned.m8n8.x4.trans.shared.b16 {%0,%1,%2,%3},[%4];"
                 : "=r"(r0), "=r"(r1), "=r"(r2), "=r"(r3) : "r"(a));
}
__device__ __forceinline__ void mma16816h(float& c0, float& c1, float& c2, float& c3,
                                          u32 a0, u32 a1, u32 a2, u32 a3, u32 b0, u32 b1) {
    asm volatile("mma.sync.aligned.m16n8k16.row.col.f32.f16.f16.f32 "
                 "{%0,%1,%2,%3},{%4,%5,%6,%7},{%8,%9},{%0,%1,%2,%3};"
                 : "+f"(c0), "+f"(c1), "+f"(c2), "+f"(c3)
                 : "r"(a0), "r"(a1), "r"(a2), "r"(a3), "r"(b0), "r"(b1));
}
__device__ __forceinline__ float ex2f(float x) {
    float r; asm("ex2.approx.f32 %0,%1;" : "=f"(r) : "f"(x)); return r;
}
__device__ __forceinline__ u32 ex2h2(u32 a) {
    u32 r; asm("ex2.approx.f16x2 %0,%1;" : "=r"(r) : "r"(a)); return r;
}
__device__ __forceinline__ u32 f2h2(float lo, float hi) {
    __half2 h = __floats2half2_rn(lo, hi);
    return *(u32*)&h;
}
__device__ __forceinline__ float hlo(u32 w) { __half2 h = *(__half2*)&w; return __low2float(h); }
__device__ __forceinline__ float hhi(u32 w) { __half2 h = *(__half2*)&w; return __high2float(h); }
__device__ __forceinline__ __half2 ash2(u32 w) { return *(__half2*)&w; }
__device__ __forceinline__ void cp16(u32 dst, const void* src) {
    asm volatile("cp.async.ca.shared.global [%0],[%1],16;" :: "r"(dst), "l"(src));
}
// PDL: wait for predecessor kernel's (implicit) launch_dependents
__device__ __forceinline__ void gdc_wait() {
    asm volatile("griddepcontrol.wait;" ::: "memory");
}

// ---------------- scratch ----------------
__device__ __half g_hb[N_NODES * DMODEL];
__device__ __half g_Wqb[DMODEL * DMODEL];
__device__ __half g_Wkb[DMODEL * DMODEL];
__device__ __half g_Wvb[DMODEL * DMODEL];
__device__ __half g_Wob[DMODEL * DMODEL];
__device__ __half g_W1b[DMODEL * HID];
__device__ __half g_W2b[HID * DMODEL];
__device__ __half g_Qb[N_NODES * DMODEL];     // pre-scaled by log2e/sqrt(dk)
__device__ __half g_Kb[N_NODES * DMODEL];
__device__ __half g_Vb[N_NODES * DMODEL];
__device__ __half g_attnb[N_NODES * DMODEL];
__device__ __half g_x2b[N_NODES * DMODEL];
__device__ __half g_Gb[N_NODES * HID];
__device__ float g_eb[NEDGE * NHEAD];         // stores 2^(eb*log2e) - 1
__device__ int   g_cnt[N_NODES];              // self-resetting (corr zeroes it)
__device__ u32   g_list[N_NODES * CAPL];
__device__ __half g_parth[KSPLIT * N_NODES * DMODEL];   // f16 O partials
__device__ float g_lp[KSPLIT * N_NODES * NHEAD];
__device__ float g_Y[N_NODES * DMODEL];
__device__ float g_h1[N_NODES * DMODEL];

// ---------------- conv + edge prep ----------------
__global__ __launch_bounds__(256) void prep_kernel(const float* __restrict__ h,
                                                   const float* __restrict__ Wq,
                                                   const float* __restrict__ Wk,
                                                   const float* __restrict__ Wv,
                                                   const float* __restrict__ Wo,
                                                   const float* __restrict__ W1,
                                                   const float* __restrict__ W2,
                                                   const float* __restrict__ ea,
                                                   const float* __restrict__ We,
                                                   const float* __restrict__ be,
                                                   const int*   __restrict__ eidx) {
    int gid = blockIdx.x * 256 + threadIdx.x;
    if (gid < 262144) {
        const float* src; __half* dst; int off;
        if (gid < 131072)      { src = h;  dst = g_hb;  off = gid; }
        else if (gid < 147456) { src = Wq; dst = g_Wqb; off = gid - 131072; }
        else if (gid < 163840) { src = Wk; dst = g_Wkb; off = gid - 147456; }
        else if (gid < 180224) { src = Wv; dst = g_Wvb; off = gid - 163840; }
        else if (gid < 196608) { src = Wo; dst = g_Wob; off = gid - 180224; }
        else if (gid < 229376) { src = W1; dst = g_W1b; off = gid - 196608; }
        else                   { src = W2; dst = g_W2b; off = gid - 229376; }
        float4 v = ((const float4*)src)[off];
        uint2 p;
        p.x = f2h2(v.x, v.y);
        p.y = f2h2(v.z, v.w);
        ((uint2*)dst)[off] = p;
    } else {
        const float L2E = 1.4426950408889634f;
        int e = gid - 262144;
        float a[7];
#pragma unroll
        for (int j = 0; j < 7; j++) a[j] = ea[e * 7 + j];
#pragma unroll
        for (int hh = 0; hh < 8; hh++) {
            float v = be[hh];
#pragma unroll
            for (int j = 0; j < 7; j++) v += a[j] * We[j * 8 + hh];
            g_eb[e * 8 + hh] = ex2f(v * L2E) - 1.f;   // 2^eb' - 1
        }
        int src = eidx[e];
        int dst = eidx[NEDGE + e];
        int pos = atomicAdd(&g_cnt[src], 1);
        if (pos < CAPL) g_list[(size_t)src * CAPL + pos] = ((u32)dst << 16) | (u32)e;
    }
}

// ---------------- fp16 tensor-core GEMM: 32x64 tile, BK=32, cp.async 4-stage ------
__device__ __forceinline__ void gemm_f16_body(const __half* __restrict__ A,
                                              const __half* __restrict__ B,
                                              const float* __restrict__ bias,
                                              const float* __restrict__ R,
                                              float* __restrict__ Cf,
                                              __half* __restrict__ Cb,
                                              int N, int K, int gelu, float oscale,
                                              int bm, int bn) {
    __shared__ __align__(16) __half As[4][32][40];
    __shared__ __align__(16) __half Bs[4][32][72];
    const int tid = threadIdx.x, warp = tid >> 5, lane = tid & 31;
    const int wm = warp & 1, wn = warp >> 1;
    const int lr = lane & 7, lm = lane >> 3;

    const int ar = tid >> 2, ac = tid & 3;
    const int br0 = tid >> 3, bc = tid & 7;
    const int br1 = br0 + 16;

    const u32 sA = su32(&As[0][0][0]);
    const u32 sB = su32(&Bs[0][0][0]);
    const u32 dstA  = sA + ar * 80 + ac * 16;
    const u32 dstB0 = sB + br0 * 144 + bc * 16;
    const u32 dstB1 = sB + br1 * 144 + bc * 16;
    const __half* srcA = A + (size_t)(bm + ar) * K + ac * 8;

    const int Kk = K >> 5;
    float acc[4][4] = {};

    auto issue = [&](int kb, int st) {
        if (kb < Kk) {
            cp16(dstA + st * 2560, srcA + kb * 32);
            cp16(dstB0 + st * 4608, B + (size_t)(kb * 32 + br0) * N + bn + bc * 8);
            cp16(dstB1 + st * 4608, B + (size_t)(kb * 32 + br1) * N + bn + bc * 8);
        }
        asm volatile("cp.async.commit_group;");
    };
    issue(0, 0);
    issue(1, 1);
    issue(2, 2);

    const u32 aBase = sA + (wm * 16 + lr + (lm & 1) * 8) * 80 + (lm >> 1) * 16;
    const u32 bBase = sB + (lr + (lm & 1) * 8) * 144 + (wn * 32 + (lm >> 1) * 8) * 2;

    for (int kb = 0; kb < Kk; kb++) {
        asm volatile("cp.async.wait_group 2;");
        __syncthreads();
        issue(kb + 3, (kb + 3) & 3);
        const u32 aS = aBase + (kb & 3) * 2560;
        const u32 bS = bBase + (kb & 3) * 4608;
#pragma unroll
        for (int ks = 0; ks < 2; ks++) {
            u32 a0, a1, a2, a3;
            ldsm_x4(a0, a1, a2, a3, aS + ks * 32);
#pragma unroll
            for (int ng2 = 0; ng2 < 2; ng2++) {
                u32 b0, b1, b2, b3;
                ldsm_x4t(b0, b1, b2, b3, bS + ks * 16 * 144 + ng2 * 32);
                mma16816h(acc[ng2 * 2][0], acc[ng2 * 2][1], acc[ng2 * 2][2], acc[ng2 * 2][3],
                          a0, a1, a2, a3, b0, b1);
                mma16816h(acc[ng2 * 2 + 1][0], acc[ng2 * 2 + 1][1],
                          acc[ng2 * 2 + 1][2], acc[ng2 * 2 + 1][3],
                          a0, a1, a2, a3, b2, b3);
            }
        }
    }

    const int rr = lane >> 2, cql = 2 * (lane & 3);
    const int r0 = bm + wm * 16 + rr, r1 = r0 + 8;
#pragma unroll
    for (int idx = 0; idx < 4; idx++) {
        const int col = bn + wn * 32 + idx * 8 + cql;
        float b0 = bias[col], b1 = bias[col + 1];
        float o0 = (acc[idx][0] + b0) * oscale, o1 = (acc[idx][1] + b1) * oscale;
        float o2 = (acc[idx][2] + b0) * oscale, o3 = (acc[idx][3] + b1) * oscale;
        if (gelu) {
            o0 *= normcdff(o0); o1 *= normcdff(o1);
            o2 *= normcdff(o2); o3 *= normcdff(o3);
        }
        if (R) {
            o0 += R[(size_t)r0 * N + col]; o1 += R[(size_t)r0 * N + col + 1];
            o2 += R[(size_t)r1 * N + col]; o3 += R[(size_t)r1 * N + col + 1];
        }
        if (Cb) {
            *(u32*)&Cb[(size_t)r0 * N + col] = f2h2(o0, o1);
            *(u32*)&Cb[(size_t)r1 * N + col] = f2h2(o2, o3);
        } else {
            *(float2*)&Cf[(size_t)r0 * N + col] = make_float2(o0, o1);
            *(float2*)&Cf[(size_t)r1 * N + col] = make_float2(o2, o3);
        }
    }
}

__global__ __launch_bounds__(128) void gemm_f16(const __half* __restrict__ A,
                                                const __half* __restrict__ B,
                                                const float* __restrict__ bias,
                                                const float* __restrict__ R,
                                                float* __restrict__ Cf,
                                                __half* __restrict__ Cb,
                                                int N, int K, int gelu) {
    gdc_wait();
    gemm_f16_body(A, B, bias, R, Cf, Cb, N, K, gelu, 1.0f, blockIdx.y * 32, blockIdx.x * 64);
}

__global__ __launch_bounds__(128) void gemm_qkv_f16(const float* __restrict__ bq,
                                                    const float* __restrict__ bk,
                                                    const float* __restrict__ bv) {
    gdc_wait();
    const float SCALE2 = 1.4426950408889634f * 0.17677669529663688f;
    int sel = blockIdx.x >> 2;
    int bn  = (blockIdx.x & 3) * 64;
    const __half* B   = (sel == 0) ? g_Wqb : (sel == 1) ? g_Wkb : g_Wvb;
    const float* bias = (sel == 0) ? bq : (sel == 1) ? bk : bv;
    __half* Cb        = (sel == 0) ? g_Qb : (sel == 1) ? g_Kb : g_Vb;
    float oscale      = (sel == 0) ? SCALE2 : 1.0f;
    gemm_f16_body(g_hb, B, bias, nullptr, nullptr, Cb, DMODEL, DMODEL, 0, oscale,
                  blockIdx.y * 32, bn);
}

// ---------------- dense flash attention: 128 q/block, split-K=8, f16x2 exp ----
__global__ __launch_bounds__(128, 3) void attn_mma(const __half* __restrict__ Qb,
                                                   const __half* __restrict__ Kb,
                                                   const __half* __restrict__ Vb) {
    __shared__ __align__(16) __half Qs[128][40];
    __shared__ __align__(16) __half Ks[3][64][40];
    __shared__ __align__(16) __half Vs[3][64][40];

    gdc_wait();

    const int h     = blockIdx.y;
    const int qb    = blockIdx.x * 128;
    const int chunk = blockIdx.z;
    const int kb0   = chunk * (N_NODES / KSPLIT);
    const int tid = threadIdx.x;
    const int warp = tid >> 5, lane = tid & 31;

#pragma unroll
    for (int i = 0; i < 4; i++) {
        int task = tid + 128 * i;
        int row = task >> 2, ch = task & 3;
        *(uint4*)((char*)&Qs[row][0] + ch * 16) =
            *(const uint4*)((const char*)(Qb + (size_t)(qb + row) * DMODEL + h * DK) + ch * 16);
    }
    __syncthreads();
    const int lr = lane & 7, lm = lane >> 3;
    u32 qa[2][2][4];
#pragma unroll
    for (int s = 0; s < 2; s++) {
        int row = warp * 32 + s * 16 + lr + (lm & 1) * 8;
#pragma unroll
        for (int c = 0; c < 2; c++) {
            u32 a = su32(&Qs[row][c * 16 + (lm >> 1) * 8]);
            ldsm_x4(qa[s][c][0], qa[s][c][1], qa[s][c][2], qa[s][c][3], a);
        }
    }

    const int row0 = tid >> 2, ch0 = tid & 3;
    const int row1 = (tid + 128) >> 2, ch1 = (tid + 128) & 3;
    const u32 kd0 = su32(&Ks[0][row0][0]) + ch0 * 16;
    const u32 kd1 = su32(&Ks[0][row1][0]) + ch1 * 16;
    const u32 vd0 = su32(&Vs[0][row0][0]) + ch0 * 16;
    const u32 vd1 = su32(&Vs[0][row1][0]) + ch1 * 16;

    auto issueT = [&](int kt, int st) {
        if (kt < ATILES) {
            int kb = kb0 + kt * 64;
            cp16(kd0 + st * 5120, (const char*)(Kb + (size_t)(kb + row0) * DMODEL + h * DK) + ch0 * 16);
            cp16(kd1 + st * 5120, (const char*)(Kb + (size_t)(kb + row1) * DMODEL + h * DK) + ch1 * 16);
            cp16(vd0 + st * 5120, (const char*)(Vb + (size_t)(kb + row0) * DMODEL + h * DK) + ch0 * 16);
            cp16(vd1 + st * 5120, (const char*)(Vb + (size_t)(kb + row1) * DMODEL + h * DK) + ch1 * 16);
        }
        asm volatile("cp.async.commit_group;");
    };
    issueT(0, 0);
    issueT(1, 1);

    const u32 kaddr = su32(&Ks[0][lr][lm * 8]);
    const u32 vaddr = su32(&Vs[0][lr + (lm & 1) * 8][(lm >> 1) * 8]);

    float O[2][4][4];
#pragma unroll
    for (int s = 0; s < 2; s++)
#pragma unroll
        for (int t = 0; t < 4; t++)
#pragma unroll
            for (int j = 0; j < 4; j++) O[s][t][j] = 0.f;
    float l[2][2] = {};

    for (int kt = 0; kt < ATILES; kt++) {
        asm volatile("cp.async.wait_group 1;");
        __syncthreads();
        issueT(kt + 2, (kt + 2) % 3);
        const u32 kS = kaddr + (kt % 3) * 5120;
        const u32 vS = vaddr + (kt % 3) * 5120;

        u32 P[2][8][2];
#pragma unroll
        for (int kg = 0; kg < 8; kg++) {
            u32 b0, b1, b2, b3;
            ldsm_x4(b0, b1, b2, b3, kS + kg * 640);
#pragma unroll
            for (int s = 0; s < 2; s++) {
                float c0 = 0.f, c1 = 0.f, c2 = 0.f, c3 = 0.f;
                mma16816h(c0, c1, c2, c3, qa[s][0][0], qa[s][0][1], qa[s][0][2], qa[s][0][3], b0, b1);
                mma16816h(c0, c1, c2, c3, qa[s][1][0], qa[s][1][1], qa[s][1][2], qa[s][1][3], b2, b3);
                u32 p01 = ex2h2(f2h2(c0, c1));
                u32 p23 = ex2h2(f2h2(c2, c3));
                l[s][0] += hlo(p01) + hhi(p01);
                l[s][1] += hlo(p23) + hhi(p23);
                P[s][kg][0] = p01;
                P[s][kg][1] = p23;
            }
        }

#pragma unroll
        for (int ck = 0; ck < 4; ck++) {
#pragma unroll
            for (int tp = 0; tp < 2; tp++) {
                u32 v0, v1, v2, v3;
                ldsm_x4t(v0, v1, v2, v3, vS + ck * 1280 + tp * 32);
#pragma unroll
                for (int s = 0; s < 2; s++) {
                    u32 a0 = P[s][2 * ck][0], a1 = P[s][2 * ck][1];
                    u32 a2 = P[s][2 * ck + 1][0], a3 = P[s][2 * ck + 1][1];
                    mma16816h(O[s][2 * tp][0], O[s][2 * tp][1], O[s][2 * tp][2], O[s][2 * tp][3],
                              a0, a1, a2, a3, v0, v1);
                    mma16816h(O[s][2 * tp + 1][0], O[s][2 * tp + 1][1],
                              O[s][2 * tp + 1][2], O[s][2 * tp + 1][3],
                              a0, a1, a2, a3, v2, v3);
                }
            }
        }
    }

    const int cql = 2 * (lane & 3);
    __half* part = g_parth + (size_t)chunk * N_NODES * DMODEL;
#pragma unroll
    for (int s = 0; s < 2; s++) {
        float l0 = l[s][0], l1 = l[s][1];
        l0 += __shfl_xor_sync(0xffffffffu, l0, 1);
        l0 += __shfl_xor_sync(0xffffffffu, l0, 2);
        l1 += __shfl_xor_sync(0xffffffffu, l1, 1);
        l1 += __shfl_xor_sync(0xffffffffu, l1, 2);
        const int r0 = qb + warp * 32 + s * 16 + (lane >> 2);
        const int r1 = r0 + 8;
#pragma unroll
        for (int t = 0; t < 4; t++) {
            int col = h * DK + t * 8 + cql;
            *(u32*)&part[(size_t)r0 * DMODEL + col] = f2h2(O[s][t][0], O[s][t][1]);
            *(u32*)&part[(size_t)r1 * DMODEL + col] = f2h2(O[s][t][2], O[s][t][3]);
        }
        if ((lane & 3) == 0) {
            g_lp[((size_t)chunk * N_NODES + r0) * NHEAD + h] = l0;
            g_lp[((size_t)chunk * N_NODES + r1) * NHEAD + h] = l1;
        }
    }
}

// ---------------- sparse bias correction + combine -> f16 attn ----------------
// block 64 = 2 warps = 1 query x 2 head-halves. lane = h_local*8 + g,
// h = warp*4 + h_local, lane owns dims [g*4, g*4+4). half2 math throughout.
__global__ __launch_bounds__(64) void corr_kernel(const __half* __restrict__ Qb,
                                                  const __half* __restrict__ Kb,
                                                  const __half* __restrict__ Vb) {
    __shared__ u32 slist[CAPL];
    __shared__ u32 wlist[CAPL];
    __shared__ int scnt;
    gdc_wait();
    const int warp = threadIdx.x >> 5;   // head half
    const int q    = blockIdx.x;
    const int lane = threadIdx.x & 31;
    const int hl = lane >> 3, g = lane & 7;
    const int h = warp * 4 + hl;
    const u32 lmask_lt = (1u << lane) - 1u;

    if (threadIdx.x == 0) { scnt = g_cnt[q]; g_cnt[q] = 0; }   // self-reset
    __syncthreads();
    int cnt = scnt;
    if (cnt > CAPL) cnt = CAPL;

    // Q slice (pre-scaled) as half2
    __half2 qh0, qh1;
    {
        uint2 wq = *(const uint2*)(Qb + (size_t)q * DMODEL + h * DK + g * 4);
        qh0 = ash2(wq.x);
        qh1 = ash2(wq.y);
    }

    // both warps load the full list (identical values - benign)
    for (int i = lane; i < cnt; i += 32)
        slist[i] = g_list[(size_t)q * CAPL + i];
    __syncwarp();

    // dedup (winner = max (dst<<16)|e per dst) + compact; duplicated per warp
    int ncnt = 0;
    for (int base = 0; base < cnt; base += 32) {
        int i = base + lane;
        u32 v = 0;
        bool win = false;
        if (i < cnt) {
            v = slist[i];
            win = true;
            for (int j = 0; j < cnt; j++) {
                u32 u = slist[j];
                if (((u ^ v) & 0xFFFF0000u) == 0 && u > v) win = false;
            }
        }
        u32 m = __ballot_sync(0xffffffffu, win);
        if (win) wlist[ncnt + __popc(m & lmask_lt)] = v;
        ncnt += __popc(m);
    }
    __syncwarp();

    __half2 Oa = __float2half2_rn(0.f), Ob = __float2half2_rn(0.f);
    float lacc = 0.f;

    uint2 kA[4], vA[4];
    float eA[4];
    auto loadb = [&](int base, uint2* kk, uint2* vv, float* ee) {
#pragma unroll
        for (int j = 0; j < 4; j++) {
            int idx = base + j;
            if (idx < ncnt) {                        // warp-uniform
                u32 v = wlist[idx];
                int k    = (int)(v >> 16);
                int widx = (int)(v & 0xFFFFu);
                kk[j] = *(const uint2*)(Kb + (size_t)k * DMODEL + h * DK + g * 4);
                vv[j] = *(const uint2*)(Vb + (size_t)k * DMODEL + h * DK + g * 4);
                ee[j] = g_eb[(size_t)widx * 8 + h];  // 2^eb - 1
            }
        }
    };
    loadb(0, kA, vA, eA);

    for (int i = 0; i < ncnt; i += 4) {
        uint2 kB[4], vB[4];
        float eB[4];
        loadb(i + 4, kB, vB, eB);                    // prefetch next batch
#pragma unroll
        for (int j = 0; j < 4; j++) {
            if (i + j >= ncnt) break;                // warp-uniform
            __half2 d = __hmul2(qh0, ash2(kA[j].x));
            d = __hfma2(qh1, ash2(kA[j].y), d);
            float s = __low2float(d) + __high2float(d);
            s += __shfl_xor_sync(0xffffffffu, s, 1);
            s += __shfl_xor_sync(0xffffffffu, s, 2);
            s += __shfl_xor_sync(0xffffffffu, s, 4);
            float pd = ex2f(s) * eA[j];              // 2^s * (2^eb - 1)
            lacc += pd;
            __half2 pdh = __float2half2_rn(pd);
            Oa = __hfma2(pdh, ash2(vA[j].x), Oa);
            Ob = __hfma2(pdh, ash2(vA[j].y), Ob);
        }
#pragma unroll
        for (int j = 0; j < 4; j++) { kA[j] = kB[j]; vA[j] = vB[j]; eA[j] = eB[j]; }
    }

    // reduce lacc across the 8-lane head group (all lanes get it)
    lacc += __shfl_xor_sync(0xffffffffu, lacc, 1);
    lacc += __shfl_xor_sync(0xffffffffu, lacc, 2);
    lacc += __shfl_xor_sync(0xffffffffu, lacc, 4);

    float O4[4] = {__low2float(Oa), __high2float(Oa), __low2float(Ob), __high2float(Ob)};

    float ltot = lacc;
#pragma unroll
    for (int c = 0; c < KSPLIT; c++)
        ltot += g_lp[((size_t)c * N_NODES + q) * NHEAD + h];
    const int col = h * DK + g * 4;
#pragma unroll
    for (int c = 0; c < KSPLIT; c++) {
        uint2 p = *(const uint2*)(g_parth + ((size_t)c * N_NODES + q) * DMODEL + col);
        O4[0] += hlo(p.x); O4[1] += hhi(p.x);
        O4[2] += hlo(p.y); O4[3] += hhi(p.y);
    }
    float inv = 1.f / ltot;
    uint2 px;
    px.x = f2h2(O4[0] * inv, O4[1] * inv);
    px.y = f2h2(O4[2] * inv, O4[3] * inv);
    *(uint2*)&g_attnb[(size_t)q * DMODEL + col] = px;
}

// ---------------- fused double LayerNorm ----------------
__global__ __launch_bounds__(256) void ln_kernel(const float* __restrict__ Y,
                                                 const float* __restrict__ g1,
                                                 const float* __restrict__ b1,
                                                 const float* __restrict__ g2,
                                                 const float* __restrict__ b2,
                                                 float* __restrict__ H1,
                                                 __half* __restrict__ X2h) {
    gdc_wait();
    const int lane = threadIdx.x & 31;
    const int row  = blockIdx.x * 8 + (threadIdx.x >> 5);
    const float4* y4 = (const float4*)(Y + (size_t)row * DMODEL);
    float v[8];
    {
        float4 a = y4[lane * 2], b = y4[lane * 2 + 1];
        v[0] = a.x; v[1] = a.y; v[2] = a.z; v[3] = a.w;
        v[4] = b.x; v[5] = b.y; v[6] = b.z; v[7] = b.w;
    }

    float s = 0.f;
#pragma unroll
    for (int j = 0; j < 8; j++) s += v[j];
#pragma unroll
    for (int o = 16; o; o >>= 1) s += __shfl_xor_sync(0xffffffffu, s, o);
    float mu = s * (1.f / 256.f);
    float q = 0.f;
#pragma unroll
    for (int j = 0; j < 8; j++) { float d = v[j] - mu; q += d * d; }
#pragma unroll
    for (int o = 16; o; o >>= 1) q += __shfl_xor_sync(0xffffffffu, q, o);
    float rs = rsqrtf(q * (1.f / 256.f) + 1e-5f);

    const int c0 = lane * 8;
    float hv[8];
#pragma unroll
    for (int j = 0; j < 8; j++)
        hv[j] = (v[j] - mu) * rs * g1[c0 + j] + b1[c0 + j];
    {
        float4* h4 = (float4*)(H1 + (size_t)row * DMODEL + c0);
        h4[0] = make_float4(hv[0], hv[1], hv[2], hv[3]);
        h4[1] = make_float4(hv[4], hv[5], hv[6], hv[7]);
    }

    s = 0.f;
#pragma unroll
    for (int j = 0; j < 8; j++) s += hv[j];
#pragma unroll
    for (int o = 16; o; o >>= 1) s += __shfl_xor_sync(0xffffffffu, s, o);
    mu = s * (1.f / 256.f);
    q = 0.f;
#pragma unroll
    for (int j = 0; j < 8; j++) { float d = hv[j] - mu; q += d * d; }
#pragma unroll
    for (int o = 16; o; o >>= 1) q += __shfl_xor_sync(0xffffffffu, q, o);
    rs = rsqrtf(q * (1.f / 256.f) + 1e-5f);

    float x[8];
#pragma unroll
    for (int j = 0; j < 8; j++)
        x[j] = (hv[j] - mu) * rs * g2[c0 + j] + b2[c0 + j];
    uint4 px;
    px.x = f2h2(x[0], x[1]);
    px.y = f2h2(x[2], x[3]);
    px.z = f2h2(x[4], x[5]);
    px.w = f2h2(x[6], x[7]);
    *(uint4*)&X2h[(size_t)row * DMODEL + c0] = px;
}

// ---------------- launch ----------------
template <typename F, typename... Args>
static inline void launch_pdl(F f, dim3 grid, dim3 block, Args... args) {
    cudaLaunchConfig_t cfg = {};
    cudaLaunchAttribute at[1];
    at[0].id = cudaLaunchAttributeProgrammaticStreamSerialization;
    at[0].val.programmaticStreamSerializationAllowed = 1;
    cfg.gridDim = grid;
    cfg.blockDim = block;
    cfg.attrs = at;
    cfg.numAttrs = 1;
    cfg.stream = 0;
    cudaLaunchKernelEx(&cfg, f, args...);
}

extern "C" void kernel_launch(void* const* d_in, const int* in_sizes, int n_in,
                              void* d_out, int out_size) {
    const float* h    = (const float*)d_in[0];
    const float* ea   = (const float*)d_in[1];
    const float* Wq   = (const float*)d_in[2];
    const float* bq   = (const float*)d_in[3];
    const float* Wk   = (const float*)d_in[4];
    const float* bk   = (const float*)d_in[5];
    const float* Wv   = (const float*)d_in[6];
    const float* bv   = (const float*)d_in[7];
    const float* Wo   = (const float*)d_in[8];
    const float* bo   = (const float*)d_in[9];
    const float* We   = (const float*)d_in[10];
    const float* be   = (const float*)d_in[11];
    const float* ln1g = (const float*)d_in[12];
    const float* ln1b = (const float*)d_in[13];
    const float* flng = (const float*)d_in[14];
    const float* flnb = (const float*)d_in[15];
    const float* W1   = (const float*)d_in[16];
    const float* b1   = (const float*)d_in[17];
    const float* W2   = (const float*)d_in[18];
    const float* b2   = (const float*)d_in[19];
    const int*   eidx = (const int*)d_in[20];
    float* out = (float*)d_out;

    __half *pQb, *pKb, *pVb, *pAttnb, *pX2b, *pGb, *pWob, *pW1b, *pW2b;
    float *pY, *pH1;
    cudaGetSymbolAddress((void**)&pQb,    g_Qb);
    cudaGetSymbolAddress((void**)&pKb,    g_Kb);
    cudaGetSymbolAddress((void**)&pVb,    g_Vb);
    cudaGetSymbolAddress((void**)&pAttnb, g_attnb);
    cudaGetSymbolAddress((void**)&pX2b,   g_x2b);
    cudaGetSymbolAddress((void**)&pGb,    g_Gb);
    cudaGetSymbolAddress((void**)&pWob,   g_Wob);
    cudaGetSymbolAddress((void**)&pW1b,   g_W1b);
    cudaGetSymbolAddress((void**)&pW2b,   g_W2b);
    cudaGetSymbolAddress((void**)&pY,     g_Y);
    cudaGetSymbolAddress((void**)&pH1,    g_h1);

    prep_kernel<<<1280, 256>>>(h, Wq, Wk, Wv, Wo, W1, W2, ea, We, be, eidx);

    launch_pdl(gemm_qkv_f16, dim3(12, 64), dim3(128), bq, bk, bv);

    launch_pdl(attn_mma, dim3(N_NODES / 128, NHEAD, KSPLIT), dim3(128),
               (const __half*)pQb, (const __half*)pKb, (const __half*)pVb);
    launch_pdl(corr_kernel, dim3(N_NODES), dim3(64),
               (const __half*)pQb, (const __half*)pKb, (const __half*)pVb);

    launch_pdl(gemm_f16, dim3(4, 64), dim3(128),
               (const __half*)pAttnb, (const __half*)pWob, bo, h, pY,
               (__half*)nullptr, DMODEL, DMODEL, 0);

    launch_pdl(ln_kernel, dim3(N_NODES / 8), dim3(256),
               (const float*)pY, ln1g, ln1b, flng, flnb, pH1, pX2b);

    launch_pdl(gemm_f16, dim3(8, 64), dim3(128),
               (const __half*)pX2b, (const __half*)pW1b, b1, (const float*)nullptr,
               (float*)nullptr, pGb, HID, DMODEL, 1);
    launch_pdl(gemm_f16, dim3(4, 64), dim3(128),
               (const __half*)pGb, (const __half*)pW2b, b2, (const float*)pH1,
               out, (__half*)nullptr, DMODEL, HID, 0);
}